// round 1
// baseline (speedup 1.0000x reference)
#include <cuda_runtime.h>
#include <cstdint>

#define N_PIX 4096
#define BATCH 4
#define CDIM  64
#define CQKD  8
#define TQ    64
#define TK    64
#define VSTR  68   // padded stride (floats) for v_s / p_s rows
#define LOG2E 1.4426950408889634f

// Scratch for q, k, v (device globals: no allocation allowed)
__device__ float g_q[BATCH * CQKD * N_PIX];
__device__ float g_k[BATCH * CQKD * N_PIX];
__device__ float g_v[BATCH * CDIM * N_PIX];

// ---------- packed f32x2 helpers (Blackwell) ----------
__device__ __forceinline__ unsigned long long ffma2(unsigned long long a,
                                                    unsigned long long b,
                                                    unsigned long long c) {
    unsigned long long d;
    asm("fma.rn.f32x2 %0, %1, %2, %3;" : "=l"(d) : "l"(a), "l"(b), "l"(c));
    return d;
}
__device__ __forceinline__ unsigned long long fmul2(unsigned long long a,
                                                    unsigned long long b) {
    unsigned long long d;
    asm("mul.rn.f32x2 %0, %1, %2;" : "=l"(d) : "l"(a), "l"(b));
    return d;
}
__device__ __forceinline__ unsigned long long packf2(float lo, float hi) {
    unsigned long long r;
    asm("mov.b64 %0, {%1, %2};" : "=l"(r) : "f"(lo), "f"(hi));
    return r;
}
__device__ __forceinline__ float2 unpackf2(unsigned long long v) {
    float lo, hi;
    asm("mov.b64 {%0, %1}, %2;" : "=f"(lo), "=f"(hi) : "l"(v));
    return make_float2(lo, hi);
}
__device__ __forceinline__ float ex2(float x) {
    float r;
    asm("ex2.approx.f32 %0, %1;" : "=f"(r) : "f"(x));
    return r;
}

// ============================================================
// Kernel 1: fused QKV projection (1x1 convs)
//   q[b,o,i] = sum_c Wq[o,c] * x[b,c,i] + bq[o]   (o < 8)
//   k, v analogous. 80 output rows total per pixel.
// ============================================================
__global__ __launch_bounds__(256) void qkv_kernel(
    const float* __restrict__ x,
    const float* __restrict__ Wq, const float* __restrict__ bq,
    const float* __restrict__ Wk, const float* __restrict__ bk,
    const float* __restrict__ Wv, const float* __restrict__ bv)
{
    __shared__ float x_s[CDIM][65];
    __shared__ float w_s[80 * 64];
    __shared__ float b_s[80];

    const int b  = blockIdx.y;
    const int i0 = blockIdx.x * 64;
    const int tid = threadIdx.x;

    for (int idx = tid; idx < 8 * 64; idx += 256)  w_s[idx]        = Wq[idx];
    for (int idx = tid; idx < 8 * 64; idx += 256)  w_s[512 + idx]  = Wk[idx];
    for (int idx = tid; idx < 64 * 64; idx += 256) w_s[1024 + idx] = Wv[idx];
    if (tid < 8)       b_s[tid] = bq[tid];
    else if (tid < 16) b_s[tid] = bk[tid - 8];
    else if (tid < 80) b_s[tid] = bv[tid - 16];

    for (int idx = tid; idx < 64 * 64; idx += 256) {
        int c = idx >> 6, p = idx & 63;
        x_s[c][p] = x[(b * CDIM + c) * N_PIX + i0 + p];
    }
    __syncthreads();

    const int og = tid >> 6;   // 0..3, uniform per warp
    const int p  = tid & 63;

    float acc[20];
#pragma unroll
    for (int k = 0; k < 20; k++) acc[k] = b_s[og * 20 + k];

#pragma unroll 8
    for (int c = 0; c < 64; c++) {
        float xv = x_s[c][p];
#pragma unroll
        for (int k = 0; k < 20; k++)
            acc[k] += w_s[(og * 20 + k) * 64 + c] * xv;
    }

#pragma unroll
    for (int k = 0; k < 20; k++) {
        int o = og * 20 + k;
        float val = acc[k];
        if (o < 8)       g_q[(b * CQKD + o) * N_PIX + i0 + p]        = val;
        else if (o < 16) g_k[(b * CQKD + (o - 8)) * N_PIX + i0 + p]  = val;
        else             g_v[(b * CDIM + (o - 16)) * N_PIX + i0 + p] = val;
    }
}

// ============================================================
// Kernel 2: flash attention + residual epilogue
//   grid (N/TQ, B), 256 threads, occupancy 2 -> single wave (256 blocks / 296 slots)
//   Thread map: ty = tid/16 -> 4 queries (q0=ty*4)
//               tx = tid%16 -> 4 keys (scores) / 4 channels (PV)
// ============================================================
__global__ __launch_bounds__(256, 2) void attn_kernel(
    const float* __restrict__ x,
    const float* __restrict__ gamma,
    float* __restrict__ out)
{
    __shared__ __align__(16) float q_s[CQKD][TQ];   // [d][q], pre-scaled by LOG2E
    __shared__ __align__(16) float k_s[CQKD][TK];   // [d][j]
    __shared__ __align__(16) float v_s[TK][VSTR];   // [j][c]
    __shared__ __align__(16) float p_s[TK][VSTR];   // [j][q]; reused as out_s[c][q]

    const int b   = blockIdx.y;
    const int i0  = blockIdx.x * TQ;
    const int tid = threadIdx.x;
    const int ty  = tid >> 4;
    const int tx  = tid & 15;
    const int q0  = ty * 4;
    const int c0  = tx * 4;

    // load + pre-scale Q tile
    for (int idx = tid; idx < CQKD * TQ; idx += 256) {
        int d = idx >> 6, q = idx & 63;
        q_s[d][q] = g_q[(b * CQKD + d) * N_PIX + i0 + q] * LOG2E;
    }

    float m[4], l[4];
    unsigned long long acc[4][2];   // f32x2 accumulators: [qq][channel pair]
#pragma unroll
    for (int qq = 0; qq < 4; qq++) {
        m[qq] = -1e30f; l[qq] = 0.f;
        acc[qq][0] = 0ull; acc[qq][1] = 0ull;
    }

    for (int t = 0; t < N_PIX / TK; t++) {
        const int j0g = t * TK;
        __syncthreads();   // previous PV done with v_s / p_s

        // K tile: k_s[d][j]
        for (int idx = tid; idx < CQKD * TK; idx += 256) {
            int d = idx >> 6, j = idx & 63;
            k_s[d][j] = g_k[(b * CQKD + d) * N_PIX + j0g + j];
        }
        // V tile transposed: v_s[j][c] (float4 global reads over j)
        for (int idx = tid; idx < (CDIM * TK) / 4; idx += 256) {
            int c = idx >> 4, u = idx & 15;
            float4 vv = *reinterpret_cast<const float4*>(
                &g_v[(b * CDIM + c) * N_PIX + j0g + u * 4]);
            v_s[u * 4 + 0][c] = vv.x;
            v_s[u * 4 + 1][c] = vv.y;
            v_s[u * 4 + 2][c] = vv.z;
            v_s[u * 4 + 3][c] = vv.w;
        }
        __syncthreads();

        // ---- scores: s[qq][jj] = sum_d q_s[d][q0+qq] * k_s[d][tx*4+jj] ----
        float s[4][4];
#pragma unroll
        for (int qq = 0; qq < 4; qq++)
#pragma unroll
            for (int jj = 0; jj < 4; jj++) s[qq][jj] = 0.f;

#pragma unroll
        for (int d = 0; d < CQKD; d++) {
            float4 qv = *reinterpret_cast<const float4*>(&q_s[d][q0]);
            float4 kv = *reinterpret_cast<const float4*>(&k_s[d][tx * 4]);
            float qa[4] = {qv.x, qv.y, qv.z, qv.w};
            float ka[4] = {kv.x, kv.y, kv.z, kv.w};
#pragma unroll
            for (int qq = 0; qq < 4; qq++)
#pragma unroll
                for (int jj = 0; jj < 4; jj++)
                    s[qq][jj] += qa[qq] * ka[jj];
        }

        // ---- online softmax (16-lane butterfly per query row) ----
        float p[4][4];
#pragma unroll
        for (int qq = 0; qq < 4; qq++) {
            float tmax = fmaxf(fmaxf(s[qq][0], s[qq][1]), fmaxf(s[qq][2], s[qq][3]));
#pragma unroll
            for (int msk = 1; msk < 16; msk <<= 1)
                tmax = fmaxf(tmax, __shfl_xor_sync(0xffffffffu, tmax, msk));
            float mnew = fmaxf(m[qq], tmax);
            float sc   = ex2(m[qq] - mnew);
            m[qq] = mnew;
            float rs = 0.f;
#pragma unroll
            for (int jj = 0; jj < 4; jj++) {
                p[qq][jj] = ex2(s[qq][jj] - mnew);
                rs += p[qq][jj];
            }
#pragma unroll
            for (int msk = 1; msk < 16; msk <<= 1)
                rs += __shfl_xor_sync(0xffffffffu, rs, msk);
            l[qq] = l[qq] * sc + rs;
            unsigned long long sc2 = packf2(sc, sc);
            acc[qq][0] = fmul2(acc[qq][0], sc2);
            acc[qq][1] = fmul2(acc[qq][1], sc2);
        }

        // store P transposed: p_s[j][q] (STS.128 per jj)
#pragma unroll
        for (int jj = 0; jj < 4; jj++) {
            float4 pv = make_float4(p[0][jj], p[1][jj], p[2][jj], p[3][jj]);
            *reinterpret_cast<float4*>(&p_s[tx * 4 + jj][q0]) = pv;
        }
        __syncthreads();

        // ---- PV: acc[qq] += p_s[j][q0+qq] * v_s[j][c0..c0+3]  (f32x2) ----
#pragma unroll 4
        for (int j = 0; j < TK; j++) {
            ulonglong2 vv = *reinterpret_cast<const ulonglong2*>(&v_s[j][c0]);
            float4 pv = *reinterpret_cast<const float4*>(&p_s[j][q0]);
            unsigned long long pb0 = packf2(pv.x, pv.x);
            unsigned long long pb1 = packf2(pv.y, pv.y);
            unsigned long long pb2 = packf2(pv.z, pv.z);
            unsigned long long pb3 = packf2(pv.w, pv.w);
            acc[0][0] = ffma2(pb0, vv.x, acc[0][0]);
            acc[0][1] = ffma2(pb0, vv.y, acc[0][1]);
            acc[1][0] = ffma2(pb1, vv.x, acc[1][0]);
            acc[1][1] = ffma2(pb1, vv.y, acc[1][1]);
            acc[2][0] = ffma2(pb2, vv.x, acc[2][0]);
            acc[2][1] = ffma2(pb2, vv.y, acc[2][1]);
            acc[3][0] = ffma2(pb3, vv.x, acc[3][0]);
            acc[3][1] = ffma2(pb3, vv.y, acc[3][1]);
        }
    }

    // ---- epilogue: normalize, stage transposed, residual + gamma ----
    __syncthreads();
#pragma unroll
    for (int qq = 0; qq < 4; qq++) {
        float il = 1.0f / l[qq];
        float2 a0 = unpackf2(acc[qq][0]);
        float2 a1 = unpackf2(acc[qq][1]);
        p_s[c0 + 0][q0 + qq] = a0.x * il;
        p_s[c0 + 1][q0 + qq] = a0.y * il;
        p_s[c0 + 2][q0 + qq] = a1.x * il;
        p_s[c0 + 3][q0 + qq] = a1.y * il;
    }
    __syncthreads();

    const float g = gamma[0];
#pragma unroll
    for (int r = 0; r < 16; r++) {
        int idx = tid + 256 * r;
        int c = idx >> 6, q = idx & 63;
        int gaddr = (b * CDIM + c) * N_PIX + i0 + q;
        out[gaddr] = g * p_s[c][q] + x[gaddr];
    }
}

extern "C" void kernel_launch(void* const* d_in, const int* in_sizes, int n_in,
                              void* d_out, int out_size)
{
    const float* x     = (const float*)d_in[0];
    const float* Wq    = (const float*)d_in[1];
    const float* bq    = (const float*)d_in[2];
    const float* Wk    = (const float*)d_in[3];
    const float* bk    = (const float*)d_in[4];
    const float* Wv    = (const float*)d_in[5];
    const float* bv    = (const float*)d_in[6];
    const float* gamma = (const float*)d_in[7];
    float* out = (float*)d_out;

    qkv_kernel<<<dim3(64, BATCH), 256>>>(x, Wq, bq, Wk, bk, Wv, bv);
    attn_kernel<<<dim3(N_PIX / TQ, BATCH), 256>>>(x, gamma, out);
}